// round 17
// baseline (speedup 1.0000x reference)
#include <cuda_runtime.h>
#include <cuda_fp16.h>
#include <cstdint>

// Problem constants
#define B_NODES 100000
#define U_NODES 50000
#define NTOT    150000
#define F_DIM   512
#define D_DIM   128
#define K_NEIGH 10
#define KOUT    1152

#define FB_BLOCKS ((B_NODES + 127) / 128)   // 782
#define NB_BLOCKS ((U_NODES + 127) / 128)   // 391

#define SMEM_SWIZZLE_128B(byte_offset) ((byte_offset) ^ (((byte_offset) >> 3) & 0x70))

// ---------------------------------------------------------------------------
// Warp-level tensor-core primitives
// ---------------------------------------------------------------------------
__device__ __forceinline__ uint32_t smem_u32(const void* p) {
    uint32_t a;
    asm("{ .reg .u64 t; cvta.to.shared.u64 t, %1; cvt.u32.u64 %0, t; }" : "=r"(a) : "l"(p));
    return a;
}

__device__ __forceinline__ void ldm_x4(uint32_t* r, uint32_t addr) {
    asm volatile("ldmatrix.sync.aligned.m8n8.x4.shared.b16 {%0,%1,%2,%3}, [%4];"
        : "=r"(r[0]), "=r"(r[1]), "=r"(r[2]), "=r"(r[3]) : "r"(addr));
}

__device__ __forceinline__ void mma_f16(float* c, const uint32_t* a,
                                        uint32_t b0, uint32_t b1) {
    asm volatile("mma.sync.aligned.m16n8k16.row.col.f32.f16.f16.f32 "
        "{%0,%1,%2,%3}, {%4,%5,%6,%7}, {%8,%9}, {%0,%1,%2,%3};"
        : "+f"(c[0]), "+f"(c[1]), "+f"(c[2]), "+f"(c[3])
        : "r"(a[0]), "r"(a[1]), "r"(a[2]), "r"(a[3]), "r"(b0), "r"(b1));
}

__device__ __forceinline__ uint32_t pack_h2(float x, float y) {
    __half2 h = __float22half2_rn(make_float2(x, y));
    return *reinterpret_cast<uint32_t*>(&h);
}

__device__ __forceinline__ void cp_async16(uint32_t dst, const void* src) {
    asm volatile("cp.async.cg.shared.global [%0], [%1], 16;" :: "r"(dst), "l"(src) : "memory");
}
#define CP_ASYNC_COMMIT() asm volatile("cp.async.commit_group;" ::: "memory")
#define CP_ASYNC_WAIT0()  asm volatile("cp.async.wait_group 0;" ::: "memory")
#define CP_ASYNC_WAIT1()  asm volatile("cp.async.wait_group 1;" ::: "memory")

#define STS128(a0, a1, a2, a3, addr) \
    asm volatile("st.shared.v4.b32 [%0], {%1, %2, %3, %4};" \
        :: "r"(addr), "r"(a0), "r"(a1), "r"(a2), "r"(a3) : "memory")

// ---------------------------------------------------------------------------
// Device-global scratch (device-code references only)
// ---------------------------------------------------------------------------
__device__ float g_s[NTOT];
__device__ __align__(16) __half g_h16[(size_t)U_NODES * D_DIM];
__device__ __align__(16) __half g_hprime16[(size_t)(B_NODES + 256) * D_DIM];
__device__ __align__(16) __half g_partial16[(size_t)B_NODES * D_DIM];
__device__ __align__(16) __half g_W16_1[(size_t)D_DIM * F_DIM];
__device__ __align__(16) __half g_W16_2[(size_t)D_DIM * KOUT];

// ---------------------------------------------------------------------------
// Merged weight transpose + fp16 rounding
// ---------------------------------------------------------------------------
__global__ void convertW_kernel(const float* __restrict__ W,
                                const float* __restrict__ Wd)
{
    int idx = blockIdx.x * blockDim.x + threadIdx.x;
    if (idx < F_DIM * D_DIM) {
        int k = idx >> 7, n = idx & 127;
        g_W16_1[(size_t)n * F_DIM + k] = __float2half_rn(W[idx]);
    } else {
        int id2 = idx - F_DIM * D_DIM;
        if (id2 >= KOUT * D_DIM) return;
        int k = id2 >> 7, n = id2 & 127;
        g_W16_2[(size_t)n * KOUT + k] = __float2half_rn(Wd[id2]);
    }
}

// ---------------------------------------------------------------------------
// UNIFIED fb+neigh kernel, 512 threads, 1 CTA/SM, DEEP pipeline:
//   A: 2 register-staging sets + 2 smem stages (LDG issued 2 chunks ahead)
//   B: 3 smem stages, cp.async groups 2 deep (wait_group 1 steady state)
//  blocks [0, FB_BLOCKS): fb pass, 128x256 tile (N=[W|Wd[0:512]]), K=512.
//  blocks [FB_BLOCKS, +NB_BLOCKS): neigh pass, 128x128 tile, h=fn@W.
// fb smem: A 2x16KB + B 3x32KB = 128KB.
// ---------------------------------------------------------------------------
__global__ void __launch_bounds__(512, 1)
fbneigh_kernel(const float* __restrict__ fb, const float* __restrict__ fn,
               const float* __restrict__ avec)
{
    constexpr int NCHUNK = F_DIM / 64;   // 8

    extern __shared__ char dsm[];
    const uint32_t ab = (smem_u32(dsm) + 1023u) & ~1023u;

    const int tid = threadIdx.x;
    const int lane = tid & 31;
    const int wid = tid >> 5;
    const int wm = wid & 3;
    const int wn = wid >> 2;
    const int lr = lane & 7;
    const int lg = lane >> 3;
    const int qm = lane >> 2;
    const int qn = (lane & 3) * 2;

    if (blockIdx.x < FB_BLOCKS) {
        // ================= FB PATH =================
        const int rowBase = blockIdx.x * 128;

        float acc[2][8][4];
        #pragma unroll
        for (int i = 0; i < 2; ++i)
            #pragma unroll
            for (int j = 0; j < 8; ++j)
                #pragma unroll
                for (int q = 0; q < 4; ++q) acc[i][j][q] = 0.f;

        float4 sa0[2][2], sa1[2][2];   // [set][iter]

        auto stA = [&](int k) { return ab + (uint32_t)(k & 1) * 16384u; };
        auto stB = [&](int k) { return ab + 32768u + (uint32_t)(k % 3) * 32768u; };

        auto issueA = [&](int k) {
            const int set = k & 1;
            const int k0c = k * 64;
            #pragma unroll
            for (int i = 0; i < 2; ++i) {
                int idx = tid + i * 512;
                int row = idx >> 3, seg = idx & 7;
                int grow = rowBase + row;
                sa0[set][i] = make_float4(0.f, 0.f, 0.f, 0.f);
                sa1[set][i] = sa0[set][i];
                if (grow < B_NODES) {
                    const float* src = fb + (size_t)grow * F_DIM + k0c + seg * 8;
                    sa0[set][i] = *(const float4*)(src);
                    sa1[set][i] = *(const float4*)(src + 4);
                }
            }
        };

        auto issueB = [&](int k) {
            const int k0c = k * 64;
            #pragma unroll
            for (int i = 0; i < 4; ++i) {
                int idx = tid + i * 512;
                int row = idx >> 3, seg = idx & 7;
                uint32_t off = SMEM_SWIZZLE_128B((uint32_t)(row * 128 + seg * 16));
                const __half* src = (row < 128)
                    ? g_W16_1 + (size_t)row * F_DIM + k0c + seg * 8
                    : g_W16_2 + (size_t)(row - 128) * KOUT + k0c + seg * 8;
                cp_async16(stB(k) + off, src);
            }
            CP_ASYNC_COMMIT();
        };

        auto commitA = [&](int k) {
            const int set = k & 1;
            #pragma unroll
            for (int i = 0; i < 2; ++i) {
                int idx = tid + i * 512;
                int row = idx >> 3, seg = idx & 7;
                uint32_t w0 = pack_h2(sa0[set][i].x, sa0[set][i].y);
                uint32_t w1 = pack_h2(sa0[set][i].z, sa0[set][i].w);
                uint32_t w2 = pack_h2(sa1[set][i].x, sa1[set][i].y);
                uint32_t w3 = pack_h2(sa1[set][i].z, sa1[set][i].w);
                uint32_t off = SMEM_SWIZZLE_128B((uint32_t)(row * 128 + seg * 16));
                STS128(w0, w1, w2, w3, stA(k) + off);
            }
        };

        auto computeChunk = [&](int k) {
            #pragma unroll
            for (int t = 0; t < 4; ++t) {
                uint32_t af[2][4];
                #pragma unroll
                for (int i = 0; i < 2; ++i) {
                    int row = wm * 32 + i * 16 + lr + (lg & 1) * 8;
                    int kb = t * 32 + (lg >> 1) * 16;
                    ldm_x4(af[i], stA(k) + SMEM_SWIZZLE_128B((uint32_t)(row * 128 + kb)));
                }
                uint32_t bfr[4][4];
                #pragma unroll
                for (int j = 0; j < 4; ++j) {
                    int row = wn * 64 + j * 16 + lr + (lg >> 1) * 8;
                    int kb = t * 32 + (lg & 1) * 16;
                    ldm_x4(bfr[j], stB(k) + SMEM_SWIZZLE_128B((uint32_t)(row * 128 + kb)));
                }
                #pragma unroll
                for (int i = 0; i < 2; ++i)
                    #pragma unroll
                    for (int j = 0; j < 4; ++j) {
                        mma_f16(acc[i][2 * j],     af[i], bfr[j][0], bfr[j][1]);
                        mma_f16(acc[i][2 * j + 1], af[i], bfr[j][2], bfr[j][3]);
                    }
            }
        };

        // ---- prologue: chunks 0 and 1 in flight ----
        issueA(0); issueB(0);
        issueA(1); issueB(1);
        commitA(0);
        CP_ASYNC_WAIT1();
        __syncthreads();

        for (int c = 0; c < NCHUNK; ++c) {
            if (c + 2 < NCHUNK) { issueA(c + 2); issueB(c + 2); }
            computeChunk(c);
            if (c + 1 < NCHUNK) {
                commitA(c + 1);
                if (c + 2 < NCHUNK) CP_ASYNC_WAIT1();
                else                CP_ASYNC_WAIT0();
            }
            __syncthreads();
        }

        // ---- epilogue ----
        float* s_sm = (float*)dsm;
        if (tid < 128) s_sm[tid] = 0.f;
        __syncthreads();

        if (wn < 2) {
            #pragma unroll
            for (int i = 0; i < 2; ++i) {
                int m0 = wm * 32 + i * 16;
                float s0 = 0.f, s1 = 0.f;
                #pragma unroll
                for (int j = 0; j < 8; ++j) {
                    int n = wn * 64 + j * 8 + qn;
                    s0 += acc[i][j][0] * avec[n] + acc[i][j][1] * avec[n + 1];
                    s1 += acc[i][j][2] * avec[n] + acc[i][j][3] * avec[n + 1];
                }
                s0 += __shfl_xor_sync(0xffffffffu, s0, 1);
                s0 += __shfl_xor_sync(0xffffffffu, s0, 2);
                s1 += __shfl_xor_sync(0xffffffffu, s1, 1);
                s1 += __shfl_xor_sync(0xffffffffu, s1, 2);
                if ((lane & 3) == 0) {
                    atomicAdd(&s_sm[m0 + qm], s0);
                    atomicAdd(&s_sm[m0 + 8 + qm], s1);
                }
            }
        } else {
            #pragma unroll
            for (int i = 0; i < 2; ++i) {
                #pragma unroll
                for (int j = 0; j < 8; ++j) {
                    int m0 = rowBase + wm * 32 + i * 16;
                    int n  = (wn - 2) * 64 + j * 8 + qn;
                    int r0 = m0 + qm, r1 = m0 + 8 + qm;
                    if (r0 < B_NODES) {
                        __half2 h = __float22half2_rn(make_float2(acc[i][j][0], acc[i][j][1]));
                        *(__half2*)(g_partial16 + (size_t)r0 * D_DIM + n) = h;
                    }
                    if (r1 < B_NODES) {
                        __half2 h = __float22half2_rn(make_float2(acc[i][j][2], acc[i][j][3]));
                        *(__half2*)(g_partial16 + (size_t)r1 * D_DIM + n) = h;
                    }
                }
            }
        }
        __syncthreads();
        if (tid < 128 && rowBase + tid < B_NODES) g_s[rowBase + tid] = s_sm[tid];

    } else {
        // ================= NEIGH PATH =================
        const int rowBase = (blockIdx.x - FB_BLOCKS) * 128;

        float acc[2][4][4];
        #pragma unroll
        for (int i = 0; i < 2; ++i)
            #pragma unroll
            for (int j = 0; j < 4; ++j)
                #pragma unroll
                for (int q = 0; q < 4; ++q) acc[i][j][q] = 0.f;

        float4 sa0[2][2], sa1[2][2];

        auto stA = [&](int k) { return ab + (uint32_t)(k & 1) * 16384u; };
        auto stB = [&](int k) { return ab + 32768u + (uint32_t)(k % 3) * 16384u; };

        auto issueA = [&](int k) {
            const int set = k & 1;
            const int k0c = k * 64;
            #pragma unroll
            for (int i = 0; i < 2; ++i) {
                int idx = tid + i * 512;
                int row = idx >> 3, seg = idx & 7;
                int grow = rowBase + row;
                sa0[set][i] = make_float4(0.f, 0.f, 0.f, 0.f);
                sa1[set][i] = sa0[set][i];
                if (grow < U_NODES) {
                    const float* src = fn + (size_t)grow * F_DIM + k0c + seg * 8;
                    sa0[set][i] = *(const float4*)(src);
                    sa1[set][i] = *(const float4*)(src + 4);
                }
            }
        };

        auto issueB = [&](int k) {
            const int k0c = k * 64;
            #pragma unroll
            for (int i = 0; i < 2; ++i) {
                int idx = tid + i * 512;
                int row = idx >> 3, seg = idx & 7;
                uint32_t off = SMEM_SWIZZLE_128B((uint32_t)(row * 128 + seg * 16));
                cp_async16(stB(k) + off, g_W16_1 + (size_t)row * F_DIM + k0c + seg * 8);
            }
            CP_ASYNC_COMMIT();
        };

        auto commitA = [&](int k) {
            const int set = k & 1;
            #pragma unroll
            for (int i = 0; i < 2; ++i) {
                int idx = tid + i * 512;
                int row = idx >> 3, seg = idx & 7;
                uint32_t w0 = pack_h2(sa0[set][i].x, sa0[set][i].y);
                uint32_t w1 = pack_h2(sa0[set][i].z, sa0[set][i].w);
                uint32_t w2 = pack_h2(sa1[set][i].x, sa1[set][i].y);
                uint32_t w3 = pack_h2(sa1[set][i].z, sa1[set][i].w);
                uint32_t off = SMEM_SWIZZLE_128B((uint32_t)(row * 128 + seg * 16));
                STS128(w0, w1, w2, w3, stA(k) + off);
            }
        };

        auto computeChunk = [&](int k) {
            #pragma unroll
            for (int t = 0; t < 4; ++t) {
                uint32_t af[2][4];
                #pragma unroll
                for (int i = 0; i < 2; ++i) {
                    int row = wm * 32 + i * 16 + lr + (lg & 1) * 8;
                    int kb = t * 32 + (lg >> 1) * 16;
                    ldm_x4(af[i], stA(k) + SMEM_SWIZZLE_128B((uint32_t)(row * 128 + kb)));
                }
                uint32_t bfr[2][4];
                #pragma unroll
                for (int j = 0; j < 2; ++j) {
                    int row = wn * 32 + j * 16 + lr + (lg >> 1) * 8;
                    int kb = t * 32 + (lg & 1) * 16;
                    ldm_x4(bfr[j], stB(k) + SMEM_SWIZZLE_128B((uint32_t)(row * 128 + kb)));
                }
                #pragma unroll
                for (int i = 0; i < 2; ++i)
                    #pragma unroll
                    for (int j = 0; j < 2; ++j) {
                        mma_f16(acc[i][2 * j],     af[i], bfr[j][0], bfr[j][1]);
                        mma_f16(acc[i][2 * j + 1], af[i], bfr[j][2], bfr[j][3]);
                    }
            }
        };

        issueA(0); issueB(0);
        issueA(1); issueB(1);
        commitA(0);
        CP_ASYNC_WAIT1();
        __syncthreads();

        for (int c = 0; c < NCHUNK; ++c) {
            if (c + 2 < NCHUNK) { issueA(c + 2); issueB(c + 2); }
            computeChunk(c);
            if (c + 1 < NCHUNK) {
                commitA(c + 1);
                if (c + 2 < NCHUNK) CP_ASYNC_WAIT1();
                else                CP_ASYNC_WAIT0();
            }
            __syncthreads();
        }

        const float* av = avec + D_DIM;
        float* s_sm = (float*)dsm;
        if (tid < 128) s_sm[tid] = 0.f;
        __syncthreads();

        #pragma unroll
        for (int i = 0; i < 2; ++i) {
            int m0 = wm * 32 + i * 16;
            int r0 = rowBase + m0 + qm, r1 = rowBase + m0 + 8 + qm;
            float s0 = 0.f, s1 = 0.f;
            #pragma unroll
            for (int j = 0; j < 4; ++j) {
                int n = wn * 32 + j * 8 + qn;
                float c0 = acc[i][j][0], c1 = acc[i][j][1];
                float c2 = acc[i][j][2], c3 = acc[i][j][3];
                s0 += c0 * av[n] + c1 * av[n + 1];
                s1 += c2 * av[n] + c3 * av[n + 1];
                if (r0 < U_NODES) {
                    __half2 h = __float22half2_rn(make_float2(c0, c1));
                    *(__half2*)(g_h16 + (size_t)r0 * D_DIM + n) = h;
                }
                if (r1 < U_NODES) {
                    __half2 h = __float22half2_rn(make_float2(c2, c3));
                    *(__half2*)(g_h16 + (size_t)r1 * D_DIM + n) = h;
                }
            }
            s0 += __shfl_xor_sync(0xffffffffu, s0, 1);
            s0 += __shfl_xor_sync(0xffffffffu, s0, 2);
            s1 += __shfl_xor_sync(0xffffffffu, s1, 1);
            s1 += __shfl_xor_sync(0xffffffffu, s1, 2);
            if ((lane & 3) == 0) {
                atomicAdd(&s_sm[m0 + qm], s0);
                atomicAdd(&s_sm[m0 + 8 + qm], s1);
            }
        }
        __syncthreads();
        if (tid < 128 && rowBase + tid < U_NODES)
            g_s[B_NODES + rowBase + tid] = s_sm[tid];
    }
}

// ---------------------------------------------------------------------------
// Aggregation: 4 nodes per block, 64 threads/node, half2 columns. (frozen)
// ---------------------------------------------------------------------------
__global__ void __launch_bounds__(256) agg_kernel(const int* __restrict__ edge_dst)
{
    const int g  = threadIdx.x >> 6;
    const int t2 = threadIdx.x & 63;
    const int i  = blockIdx.x * 4 + g;

    __shared__ float w[4][K_NEIGH];
    __shared__ int   jj[4][K_NEIGH];
    if (i < B_NODES && t2 < K_NEIGH) {
        int j = edge_dst[(size_t)i * K_NEIGH + t2];
        float sc = g_s[i] + g_s[B_NODES + j];
        float lr = sc > 0.f ? sc : 0.2f * sc;
        w[g][t2]  = expf(-lr);
        jj[g][t2] = j;
    }
    __syncthreads();
    if (i >= B_NODES) return;

    float ax = 0.f, ay = 0.f, tot = 0.f;
    #pragma unroll
    for (int k = 0; k < K_NEIGH; ++k) {
        float wk = w[g][k];
        tot += wk;
        __half2 hv = *(const __half2*)(g_h16 + (size_t)jj[g][k] * D_DIM + t2 * 2);
        float2 f = __half22float2(hv);
        ax += wk * f.x;
        ay += wk * f.y;
    }
    float vx = ax / tot, vy = ay / tot;
    if (!isfinite(vx)) vx = 0.f;
    if (!isfinite(vy)) vy = 0.f;
    *(__half2*)(g_hprime16 + (size_t)i * D_DIM + t2 * 2) =
        __float22half2_rn(make_float2(vx, vy));
}

// ---------------------------------------------------------------------------
// GEMM2: out = relu(partial + [h'|nf] @ Wd[512:1152])  (frozen, round-15)
// ---------------------------------------------------------------------------
__global__ void __launch_bounds__(256, 2)
gemm2_kernel(const float* __restrict__ nf, float* __restrict__ outp)
{
    constexpr int NCHUNK = 10;

    extern __shared__ char dsm[];
    const uint32_t ab = (smem_u32(dsm) + 1023u) & ~1023u;

    const int tid = threadIdx.x;
    const int lane = tid & 31;
    const int wm = (tid >> 5) & 3;
    const int wn = (tid >> 5) >> 2;
    const int rowBase = blockIdx.x * 128;

    float acc[2][8][4];
    #pragma unroll
    for (int i = 0; i < 2; ++i)
        #pragma unroll
        for (int j = 0; j < 8; ++j)
            #pragma unroll
            for (int q = 0; q < 4; ++q) acc[i][j][q] = 0.f;

    const int lr = lane & 7;
    const int lg = lane >> 3;

    float4 sa0[4], sa1[4];

    auto stA = [&](int s) { return ab + (uint32_t)s * 32768u; };
    auto stB = [&](int s) { return ab + (uint32_t)s * 32768u + 16384u; };

    auto issueLoads = [&](int c, int s) {
        const int k0 = 512 + c * 64;
        if (c < 2) {
            #pragma unroll
            for (int i = 0; i < 4; ++i) {
                int idx = tid + i * 256;
                int row = idx >> 3, seg = idx & 7;
                int grow = rowBase + row;
                uint32_t off = SMEM_SWIZZLE_128B((uint32_t)(row * 128 + seg * 16));
                cp_async16(stA(s) + off,
                           g_hprime16 + (size_t)grow * D_DIM + (k0 - 512) + seg * 8);
            }
        } else {
            #pragma unroll
            for (int i = 0; i < 4; ++i) {
                int idx = tid + i * 256;
                int row = idx >> 3, seg = idx & 7;
                int grow = rowBase + row;
                sa0[i] = make_float4(0.f, 0.f, 0.f, 0.f);
                sa1[i] = sa0[i];
                if (grow < B_NODES) {
                    const float* src = nf + (size_t)grow * F_DIM + (k0 - 640) + seg * 8;
                    sa0[i] = *(const float4*)(src);
                    sa1[i] = *(const float4*)(src + 4);
                }
            }
        }
        #pragma unroll
        for (int i = 0; i < 4; ++i) {
            int idx = tid + i * 256;
            int row = idx >> 3, seg = idx & 7;
            uint32_t off = SMEM_SWIZZLE_128B((uint32_t)(row * 128 + seg * 16));
            cp_async16(stB(s) + off, g_W16_2 + (size_t)row * KOUT + k0 + seg * 8);
        }
        CP_ASYNC_COMMIT();
    };

    auto commitLoads = [&](int c, int s) {
        if (c >= 2) {
            #pragma unroll
            for (int i = 0; i < 4; ++i) {
                int idx = tid + i * 256;
                int row = idx >> 3, seg = idx & 7;
                uint32_t w0 = pack_h2(sa0[i].x, sa0[i].y);
                uint32_t w1 = pack_h2(sa0[i].z, sa0[i].w);
                uint32_t w2 = pack_h2(sa1[i].x, sa1[i].y);
                uint32_t w3 = pack_h2(sa1[i].z, sa1[i].w);
                uint32_t off = SMEM_SWIZZLE_128B((uint32_t)(row * 128 + seg * 16));
                STS128(w0, w1, w2, w3, stA(s) + off);
            }
        }
        CP_ASYNC_WAIT0();
    };

    auto computeChunk = [&](int s) {
        #pragma unroll
        for (int t = 0; t < 4; ++t) {
            uint32_t af[2][4];
            #pragma unroll
            for (int i = 0; i < 2; ++i) {
                int row = wm * 32 + i * 16 + lr + (lg & 1) * 8;
                int kb = t * 32 + (lg >> 1) * 16;
                ldm_x4(af[i], stA(s) + SMEM_SWIZZLE_128B((uint32_t)(row * 128 + kb)));
            }
            uint32_t bfr[4][4];
            #pragma unroll
            for (int j = 0; j < 4; ++j) {
                int row = wn * 64 + j * 16 + lr + (lg >> 1) * 8;
                int kb = t * 32 + (lg & 1) * 16;
                ldm_x4(bfr[j], stB(s) + SMEM_SWIZZLE_128B((uint32_t)(row * 128 + kb)));
            }
            #pragma unroll
            for (int i = 0; i < 2; ++i)
                #pragma unroll
                for (int j = 0; j < 4; ++j) {
                    mma_f16(acc[i][2 * j],     af[i], bfr[j][0], bfr[j][1]);
                    mma_f16(acc[i][2 * j + 1], af[i], bfr[j][2], bfr[j][3]);
                }
        }
    };

    issueLoads(0, 0);
    commitLoads(0, 0);
    __syncthreads();

    for (int c = 0; c < NCHUNK; ++c) {
        const int cur = c & 1, nxt = (c + 1) & 1;
        if (c + 1 < NCHUNK) issueLoads(c + 1, nxt);
        computeChunk(cur);
        if (c + 1 < NCHUNK) commitLoads(c + 1, nxt);
        __syncthreads();
    }

    const int qm = lane >> 2;
    const int qn = (lane & 3) * 2;
    #pragma unroll
    for (int i = 0; i < 2; ++i) {
        #pragma unroll
        for (int j = 0; j < 8; ++j) {
            int m0 = rowBase + wm * 32 + i * 16;
            int n  = wn * 64 + j * 8 + qn;
            int r0 = m0 + qm, r1 = m0 + 8 + qm;
            if (r0 < B_NODES) {
                __half2 p = *(const __half2*)(g_partial16 + (size_t)r0 * D_DIM + n);
                float2 pf = __half22float2(p);
                float c0 = fmaxf(acc[i][j][0] + pf.x, 0.f);
                float c1 = fmaxf(acc[i][j][1] + pf.y, 0.f);
                *(float2*)(outp + (size_t)r0 * D_DIM + n) = make_float2(c0, c1);
            }
            if (r1 < B_NODES) {
                __half2 p = *(const __half2*)(g_partial16 + (size_t)r1 * D_DIM + n);
                float2 pf = __half22float2(p);
                float c2 = fmaxf(acc[i][j][2] + pf.x, 0.f);
                float c3 = fmaxf(acc[i][j][3] + pf.y, 0.f);
                *(float2*)(outp + (size_t)r1 * D_DIM + n) = make_float2(c2, c3);
            }
        }
    }
}

// ---------------------------------------------------------------------------
// Launch
// Inputs: 0=feats_batch 1=feats_neigh 2=neigh_feats 3=W 4=a 5=Wd 6=edge_src 7=edge_dst
// ---------------------------------------------------------------------------
extern "C" void kernel_launch(void* const* d_in, const int* in_sizes, int n_in,
                              void* d_out, int out_size)
{
    const float* fb   = (const float*)d_in[0];
    const float* fn   = (const float*)d_in[1];
    const float* nf   = (const float*)d_in[2];
    const float* W    = (const float*)d_in[3];
    const float* avec = (const float*)d_in[4];
    const float* Wd   = (const float*)d_in[5];
    const int* edge_dst = (const int*)d_in[7];
    float* out = (float*)d_out;
    (void)in_sizes; (void)n_in; (void)out_size;

    const int SMEM_FB  = 132096;   // A 2x16KB + B 3x32KB = 128KB + align
    const int SMEM_STD = 66560;    // 2 x 32KB + align
    cudaFuncSetAttribute(fbneigh_kernel, cudaFuncAttributeMaxDynamicSharedMemorySize, SMEM_FB);
    cudaFuncSetAttribute(gemm2_kernel,   cudaFuncAttributeMaxDynamicSharedMemorySize, SMEM_STD);

    // 0) merged weight convert
    int convN = (F_DIM + KOUT) * D_DIM;
    convertW_kernel<<<(convN + 255) / 256, 256>>>(W, Wd);

    // 1) unified fb + neigh pass (deep pipeline)
    fbneigh_kernel<<<FB_BLOCKS + NB_BLOCKS, 512, SMEM_FB>>>(fb, fn, avec);

    // 2) aggregation -> fp16 h'
    agg_kernel<<<(B_NODES + 3) / 4, 256>>>(edge_dst);

    // 3) out = relu(partial + [h'|nf]@Wd[512:])
    gemm2_kernel<<<(B_NODES + 127) / 128, 256, SMEM_STD>>>(nf, out);
}